// round 16
// baseline (speedup 1.0000x reference)
#include <cuda_runtime.h>
#include <cuda_bf16.h>
#include <math.h>
#include <stdint.h>

#define MAXN 100000
#define MAXE 1600000
#define D_IN 48
#define HID 256
#define HH 128
#define NOUT 40

typedef __nv_bfloat16 bf16;

// ---------------- scratch (device globals; no allocation allowed) ----------
__device__ __align__(256) bf16 g_xh [(size_t)MAXN * D_IN], g_xl [(size_t)MAXN * D_IN];
__device__ __align__(256) bf16 g_c1h[(size_t)MAXN * D_IN], g_c1l[(size_t)MAXN * D_IN];
__device__ __align__(256) bf16 g_cbh[(size_t)MAXN * HH],  g_cbl[(size_t)MAXN * HH];
__device__ __align__(256) bf16 g_th [(size_t)MAXN * HID], g_tl [(size_t)MAXN * HID];
__device__ __align__(256) bf16 g_h1h[(size_t)MAXN * HH],  g_h1l[(size_t)MAXN * HH];
__device__ __align__(256) bf16 g_h2h[(size_t)MAXN * HH],  g_h2l[(size_t)MAXN * HH];
// CSR
__device__ __align__(256) int g_deg[MAXN];
__device__ __align__(256) int g_rows[MAXN];
__device__ __align__(256) int g_cursor[MAXN];
__device__ __align__(256) int g_bsum[128];
__device__ __align__(256) int g_ssrc[MAXE];
// weights, transposed to [Npad, K] and hi/lo split
__device__ __align__(256) bf16 g_W1ah[256*96],  g_W1al[256*96];
__device__ __align__(256) bf16 g_W1bh[128*256], g_W1bl[128*256];
__device__ __align__(256) bf16 g_W2ah[256*304], g_W2al[256*304];
__device__ __align__(256) bf16 g_W2bh[128*256], g_W2bl[128*256];
__device__ __align__(256) bf16 g_W3ah[256*304], g_W3al[256*304];
__device__ __align__(256) bf16 g_W3bh[64*256],  g_W3bl[64*256];

// ---------------- PTX helpers (family-common: sm_80-era only) --------------
__device__ __forceinline__ uint32_t sm_u32(const void* p) {
    uint32_t a;
    asm("{ .reg .u64 t; cvta.to.shared.u64 t, %1; cvt.u32.u64 %0, t; }" : "=r"(a) : "l"(p));
    return a;
}
__device__ __forceinline__ void cp16(uint32_t dst, const void* src, bool ok) {
    int sz = ok ? 16 : 0;
    asm volatile("cp.async.cg.shared.global [%0], [%1], 16, %2;"
                 :: "r"(dst), "l"(src), "r"(sz) : "memory");
}
__device__ __forceinline__ void cp_commit() {
    asm volatile("cp.async.commit_group;" ::: "memory");
}
__device__ __forceinline__ void ldsm4(uint32_t& r0, uint32_t& r1, uint32_t& r2, uint32_t& r3,
                                      uint32_t a) {
    asm volatile("ldmatrix.sync.aligned.m8n8.x4.shared.b16 {%0,%1,%2,%3}, [%4];"
                 : "=r"(r0), "=r"(r1), "=r"(r2), "=r"(r3) : "r"(a));
}
__device__ __forceinline__ void mma16816(float* c, const uint32_t* a, const uint32_t* b) {
    asm volatile("mma.sync.aligned.m16n8k16.row.col.f32.bf16.bf16.f32 "
                 "{%0,%1,%2,%3}, {%4,%5,%6,%7}, {%8,%9}, {%0,%1,%2,%3};"
                 : "+f"(c[0]), "+f"(c[1]), "+f"(c[2]), "+f"(c[3])
                 : "r"(a[0]), "r"(a[1]), "r"(a[2]), "r"(a[3]), "r"(b[0]), "r"(b[1]));
}

// ---------------- fused 3-pass mma.sync GEMM (round-9 frozen config) -------
// Per k-tile stage holds {Ahi, Alo, Bh, Bl}; issues Ahi*Bh + Ahi*Bl + Alo*Bh
// into the same fp32 accumulators. BM=128, BK=32, 3-stage cp.async pipeline.
// MODE 0: relu -> bf16 hi/lo
// MODE 2: log_softmax (first 40 cols) -> fp32, row stride 40
template<int NB, int MODE>
__global__ __launch_bounds__(256)
void gemm_mma(const bf16* __restrict__ a0h, const bf16* __restrict__ a0l, int w0,
              const bf16* __restrict__ a1h, const bf16* __restrict__ a1l, int w1,
              const bf16* __restrict__ a2h, const bf16* __restrict__ a2l, int w2,
              int Kp,
              const bf16* __restrict__ Bh, const bf16* __restrict__ Bl,
              const float* __restrict__ bias,
              float* __restrict__ outF, bf16* __restrict__ outHi, bf16* __restrict__ outLo,
              int M, int ldo) {
    extern __shared__ char dyn[];
    constexpr int ASZ = 128 * 64;
    constexpr int BSZ = NB * 64;
    constexpr int STG = 2 * ASZ + 2 * BSZ;
    constexpr int WM  = (NB == 128) ? 2 : 4;
    constexpr int MF  = (128 / WM) / 16;
    constexpr int NF  = 4;

    const uint32_t raw  = sm_u32(dyn);
    const uint32_t base = (raw + 1023u) & ~1023u;
    const int tid  = threadIdx.x;
    const int w    = tid >> 5;
    const int lane = tid & 31;
    const int blockM = blockIdx.y * 128;
    const int blockN = blockIdx.x * NB;
    const int wm = (NB == 128) ? (w >> 2) : (w >> 1);
    const int wn = (NB == 128) ? (w & 3)  : (w & 1);
    const int wmBase = wm * (128 / WM);
    const int nBase  = wn * 32;

    const int KT  = (Kp + 31) >> 5;
    const int w01 = w0 + w1;

    const int r8 = lane & 7, mi = lane >> 3;
    uint32_t addrA[MF][2], addrB[NF / 2][2];
    #pragma unroll
    for (int i = 0; i < MF; ++i) {
        int row = wmBase + i * 16 + ((mi & 1) << 3) + r8;
        int s   = (row >> 1) & 3;
        #pragma unroll
        for (int ks = 0; ks < 2; ++ks) {
            int c = (ks << 1) + (mi >> 1);
            addrA[i][ks] = base + row * 64 + ((c ^ s) << 4);
        }
    }
    #pragma unroll
    for (int jp = 0; jp < NF / 2; ++jp) {
        int row = nBase + jp * 16 + ((mi >> 1) << 3) + r8;
        int s   = (row >> 1) & 3;
        #pragma unroll
        for (int ks = 0; ks < 2; ++ks) {
            int c = (ks << 1) + (mi & 1);
            addrB[jp][ks] = base + 2 * ASZ + row * 64 + ((c ^ s) << 4);
        }
    }

    float acc[MF][NF][4];
    #pragma unroll
    for (int i = 0; i < MF; ++i)
        #pragma unroll
        for (int j = 0; j < NF; ++j)
            #pragma unroll
            for (int q = 0; q < 4; ++q) acc[i][j][q] = 0.f;

    auto load_tile = [&](int t) {
        const int kb = t * 32;
        const uint32_t sAh = base + (t % 3) * STG;
        const uint32_t sAl = sAh + ASZ;
        const uint32_t sBh = sAh + 2 * ASZ;
        const uint32_t sBl = sBh + BSZ;
        #pragma unroll
        for (int i = 0; i < 2; ++i) {
            int id  = tid + i * 256;
            int row = id >> 2, ch = id & 3;
            int kk  = kb + ch * 8;
            int m   = blockM + row;
            bool ok = (m < M) && (kk < Kp);
            const bf16 *gh = a0h, *gl = a0l; int ld = w0, off = kk;
            if (kk < w0)       { gh = a0h; gl = a0l; ld = w0; off = kk; }
            else if (kk < w01) { gh = a1h; gl = a1l; ld = w1; off = kk - w0; }
            else               { gh = a2h; gl = a2l; ld = w2; off = kk - w01; }
            int sw = ch ^ ((row >> 1) & 3);
            cp16(sAh + row * 64 + (sw << 4),
                 ok ? (const void*)(gh + (size_t)m * ld + off) : (const void*)a0h, ok);
            cp16(sAl + row * 64 + (sw << 4),
                 ok ? (const void*)(gl + (size_t)m * ld + off) : (const void*)a0h, ok);
        }
        #pragma unroll
        for (int i = 0; i < NB / 64; ++i) {
            int id  = tid + i * 256;
            int row = id >> 2, ch = id & 3;
            int kk  = kb + ch * 8;
            bool ok = (kk < Kp);
            int sw = ch ^ ((row >> 1) & 3);
            cp16(sBh + row * 64 + (sw << 4),
                 ok ? (const void*)(Bh + (size_t)(blockN + row) * Kp + kk) : (const void*)Bh, ok);
            cp16(sBl + row * 64 + (sw << 4),
                 ok ? (const void*)(Bl + (size_t)(blockN + row) * Kp + kk) : (const void*)Bl, ok);
        }
        cp_commit();
    };

    load_tile(0);
    if (KT > 1) load_tile(1);

    for (int t = 0; t < KT; ++t) {
        if (t + 2 <= KT) asm volatile("cp.async.wait_group 1;" ::: "memory");
        else             asm volatile("cp.async.wait_group 0;" ::: "memory");
        __syncthreads();
        if (t + 2 < KT) load_tile(t + 2);

        const uint32_t stOff = (t % 3) * STG;
        #pragma unroll
        for (int ks = 0; ks < 2; ++ks) {
            uint32_t ah[MF][4], al[MF][4], bh[NF][2], bl[NF][2];
            #pragma unroll
            for (int jp = 0; jp < NF / 2; ++jp)
                ldsm4(bh[jp*2][0], bh[jp*2][1], bh[jp*2+1][0], bh[jp*2+1][1],
                      addrB[jp][ks] + stOff);
            #pragma unroll
            for (int i = 0; i < MF; ++i)
                ldsm4(ah[i][0], ah[i][1], ah[i][2], ah[i][3], addrA[i][ks] + stOff);
            #pragma unroll
            for (int i = 0; i < MF; ++i)
                #pragma unroll
                for (int j = 0; j < NF; ++j)
                    mma16816(acc[i][j], ah[i], bh[j]);
            #pragma unroll
            for (int jp = 0; jp < NF / 2; ++jp)
                ldsm4(bl[jp*2][0], bl[jp*2][1], bl[jp*2+1][0], bl[jp*2+1][1],
                      addrB[jp][ks] + stOff + BSZ);
            #pragma unroll
            for (int i = 0; i < MF; ++i)
                #pragma unroll
                for (int j = 0; j < NF; ++j)
                    mma16816(acc[i][j], ah[i], bl[j]);
            #pragma unroll
            for (int i = 0; i < MF; ++i)
                ldsm4(al[i][0], al[i][1], al[i][2], al[i][3], addrA[i][ks] + stOff + ASZ);
            #pragma unroll
            for (int i = 0; i < MF; ++i)
                #pragma unroll
                for (int j = 0; j < NF; ++j)
                    mma16816(acc[i][j], al[i], bh[j]);
        }
    }

    const int g4 = lane >> 2, t2 = lane & 3;
    if (MODE == 2) {
        __syncthreads();
        float* sl = (float*)(dyn + (base - raw));
        #pragma unroll
        for (int i = 0; i < MF; ++i) {
            int rl = wmBase + i * 16 + g4;
            #pragma unroll
            for (int j = 0; j < NF; ++j) {
                int col = nBase + j * 8 + t2 * 2;
                float b0 = (col < NOUT) ? __ldg(bias + col) : 0.f;
                float b1 = (col + 1 < NOUT) ? __ldg(bias + col + 1) : 0.f;
                sl[rl * 65 + col]           = acc[i][j][0] + b0;
                sl[rl * 65 + col + 1]       = acc[i][j][1] + b1;
                sl[(rl + 8) * 65 + col]     = acc[i][j][2] + b0;
                sl[(rl + 8) * 65 + col + 1] = acc[i][j][3] + b1;
            }
        }
        __syncthreads();
        if (tid < 128) {
            int m = blockM + tid;
            if (m < M) {
                const float* r = sl + tid * 65;
                float mx = -INFINITY;
                #pragma unroll
                for (int c = 0; c < NOUT; ++c) mx = fmaxf(mx, r[c]);
                float s = 0.f;
                #pragma unroll
                for (int c = 0; c < NOUT; ++c) s += expf(r[c] - mx);
                float lse = mx + logf(s);
                #pragma unroll
                for (int c = 0; c < NOUT; ++c) outF[(size_t)m * NOUT + c] = r[c] - lse;
            }
        }
    } else {
        #pragma unroll
        for (int i = 0; i < MF; ++i) {
            int r0 = blockM + wmBase + i * 16 + g4;
            #pragma unroll
            for (int j = 0; j < NF; ++j) {
                int colg = blockN + nBase + j * 8 + t2 * 2;
                float b0 = __ldg(bias + colg), b1 = __ldg(bias + colg + 1);
                #pragma unroll
                for (int h = 0; h < 2; ++h) {
                    int m = r0 + h * 8;
                    if (m < M) {
                        float v0 = fmaxf(acc[i][j][h * 2 + 0] + b0, 0.f);
                        float v1 = fmaxf(acc[i][j][h * 2 + 1] + b1, 0.f);
                        bf16 h0 = __float2bfloat16(v0);
                        bf16 h1 = __float2bfloat16(v1);
                        __nv_bfloat162 hp; hp.x = h0; hp.y = h1;
                        __nv_bfloat162 lp;
                        lp.x = __float2bfloat16(v0 - __bfloat162float(h0));
                        lp.y = __float2bfloat16(v1 - __bfloat162float(h1));
                        *(__nv_bfloat162*)(outHi + (size_t)m * ldo + colg) = hp;
                        *(__nv_bfloat162*)(outLo + (size_t)m * ldo + colg) = lp;
                    }
                }
            }
        }
    }
}

// ---------------- fused elementwise prologue + histogram -------------------
__device__ __forceinline__ void wsplit_one(const float* __restrict__ W, int K, int Nn,
                                           int i, bf16* __restrict__ bh,
                                           bf16* __restrict__ bl) {
    int n = i / K, k = i - n * K;
    float v = (n < Nn) ? W[(size_t)k * Nn + n] : 0.f;
    bf16 h = __float2bfloat16(v);
    bh[i] = h;
    bl[i] = __float2bfloat16(v - __bfloat162float(h));
}

__global__ void zero_deg_kernel(int* __restrict__ deg, int n4) {
    int i = blockIdx.x * blockDim.x + threadIdx.x;
    if (i < n4) ((int4*)deg)[i] = make_int4(0, 0, 0, 0);
}

// prep: x split + 6 weight splits + degree histogram (deg pre-zeroed)
__global__ void prep_kernel(const float* __restrict__ x, bf16* __restrict__ xh,
                            bf16* __restrict__ xl, int nx,
                            const int* __restrict__ dst, int E, int* __restrict__ deg,
                            const float* W1a, bf16* W1ah, bf16* W1al,
                            const float* W1b, bf16* W1bh, bf16* W1bl,
                            const float* W2a, bf16* W2ah, bf16* W2al,
                            const float* W2b, bf16* W2bh, bf16* W2bl,
                            const float* W3a, bf16* W3ah, bf16* W3al,
                            const float* W3b, bf16* W3bh, bf16* W3bl) {
    const int C1 = 256 * 96, C2 = 128 * 256, C3 = 256 * 304, C6 = 64 * 256;
    const int S1 = nx;
    const int E1 = S1 + C1, E2 = E1 + C2, E3 = E2 + C3;
    const int E4 = E3 + C2, E5 = E4 + C3, E6 = E5 + C6;
    const int H  = (E + 3) >> 2;
    const int E7 = E6 + H;
    int i  = blockIdx.x * blockDim.x + threadIdx.x;
    int st = gridDim.x * blockDim.x;
    for (; i < E7; i += st) {
        if (i < S1) {
            float v = x[i];
            bf16 h = __float2bfloat16(v);
            xh[i] = h;
            xl[i] = __float2bfloat16(v - __bfloat162float(h));
        }
        else if (i < E1) wsplit_one(W1a, 96, 256, i - S1, W1ah, W1al);
        else if (i < E2) wsplit_one(W1b, 256, 128, i - E1, W1bh, W1bl);
        else if (i < E3) wsplit_one(W2a, 304, 256, i - E2, W2ah, W2al);
        else if (i < E4) wsplit_one(W2b, 256, 128, i - E3, W2bh, W2bl);
        else if (i < E5) wsplit_one(W3a, 304, 256, i - E4, W3ah, W3al);
        else if (i < E6) wsplit_one(W3b, 256, NOUT, i - E5, W3bh, W3bl);
        else {
            int b = (i - E6) * 4;
            if (b + 3 < E) {
                int4 d4 = __ldg((const int4*)(dst + b));
                atomicAdd(deg + d4.x, 1);
                atomicAdd(deg + d4.y, 1);
                atomicAdd(deg + d4.z, 1);
                atomicAdd(deg + d4.w, 1);
            } else {
                for (int e = b; e < E; ++e) atomicAdd(deg + __ldg(dst + e), 1);
            }
        }
    }
}

// ---------------- CSR build ----------------
// 1024-thread block scan via warp shuffles (2 syncthreads total)
__global__ void scan1_kernel(const int* __restrict__ deg, int* __restrict__ rows,
                             int* __restrict__ bsum, int n) {
    __shared__ int wsum[32];
    int gid = blockIdx.x * 1024 + threadIdx.x;
    int lane = threadIdx.x & 31;
    int wid  = threadIdx.x >> 5;
    int v = (gid < n) ? deg[gid] : 0;
    int s = v;
    #pragma unroll
    for (int o = 1; o < 32; o <<= 1) {
        int t = __shfl_up_sync(0xffffffffu, s, o);
        if (lane >= o) s += t;
    }
    if (lane == 31) wsum[wid] = s;
    __syncthreads();
    if (wid == 0) {
        int ws = wsum[lane];
        #pragma unroll
        for (int o = 1; o < 32; o <<= 1) {
            int t = __shfl_up_sync(0xffffffffu, ws, o);
            if (lane >= o) ws += t;
        }
        wsum[lane] = ws;
        if (lane == 31 && blockIdx.x < 128) bsum[blockIdx.x] = ws;
    }
    __syncthreads();
    int excl = s - v + (wid > 0 ? wsum[wid - 1] : 0);
    if (gid < n) rows[gid] = excl;
}
// fused scan2+scan3: each block re-scans bsum locally (nb <= 128)
__global__ void scan23_kernel(int* __restrict__ rows, int* __restrict__ cursor,
                              const int* __restrict__ bsum, int n, int nb) {
    __shared__ int sh[128];
    int i = threadIdx.x;
    int v = 0;
    if (i < 128) {
        v = (i < nb) ? bsum[i] : 0;
        sh[i] = v;
    }
    __syncthreads();
    #pragma unroll
    for (int o = 1; o < 128; o <<= 1) {
        int t = (i < 128 && i >= o) ? sh[i - o] : 0;
        __syncthreads();
        if (i < 128) sh[i] += t;
        __syncthreads();
    }
    if (i < 128) sh[i] -= v;          // exclusive prefix
    __syncthreads();
    int gid = blockIdx.x * blockDim.x + threadIdx.x;
    if (gid < n) {
        int r = rows[gid] + sh[gid >> 10];
        rows[gid] = r;
        cursor[gid] = r;
    }
}
// 4 edges per thread, int4 index loads
__global__ void permute_kernel(const int* __restrict__ src, const int* __restrict__ dst,
                               int* __restrict__ cursor, int* __restrict__ ssrc, int E) {
    int t = blockIdx.x * blockDim.x + threadIdx.x;
    int b = t * 4;
    if (b + 3 < E) {
        int4 d4 = __ldg((const int4*)(dst + b));
        int4 s4 = __ldg((const int4*)(src + b));
        ssrc[atomicAdd(cursor + d4.x, 1)] = s4.x;
        ssrc[atomicAdd(cursor + d4.y, 1)] = s4.y;
        ssrc[atomicAdd(cursor + d4.z, 1)] = s4.z;
        ssrc[atomicAdd(cursor + d4.w, 1)] = s4.w;
    } else {
        for (int e = b; e < E; ++e) {
            int d = __ldg(dst + e);
            ssrc[atomicAdd(cursor + d, 1)] = __ldg(src + e);
        }
    }
}

// ---------------- gather-sum convs ----------------
// Layer-2/3 gather: reads HI array only (bf16-quantized conv input; error
// ~2^-10/sqrt(deg), well under tolerance). Lanes 0-15 even edges, 16-31 odd;
// each lane loads one uint4 (8 cols) -> 256B/edge. Merge via shfl_down(16).
__global__ void conv_gather128_bf(const bf16* __restrict__ xhp,
                                  const int* __restrict__ rows, const int* __restrict__ deg,
                                  const int* __restrict__ ssrc,
                                  bf16* __restrict__ oh, bf16* __restrict__ ol, int N) {
    int warp = (blockIdx.x * blockDim.x + threadIdx.x) >> 5;
    int lane = threadIdx.x & 31;
    if (warp >= N) return;
    const int half = lane >> 4;
    const int q    = lane & 15;
    int rs = __ldg(rows + warp), dg = __ldg(deg + warp);
    float a[8];
    #pragma unroll
    for (int k = 0; k < 8; ++k) a[k] = 0.f;

    #define ACC8(v) { \
        float2 p0 = __bfloat1622float2(*(__nv_bfloat162*)&(v).x); \
        float2 p1 = __bfloat1622float2(*(__nv_bfloat162*)&(v).y); \
        float2 p2 = __bfloat1622float2(*(__nv_bfloat162*)&(v).z); \
        float2 p3 = __bfloat1622float2(*(__nv_bfloat162*)&(v).w); \
        a[0] += p0.x; a[1] += p0.y; a[2] += p1.x; a[3] += p1.y; \
        a[4] += p2.x; a[5] += p2.y; a[6] += p3.x; a[7] += p3.y; }

    for (int jb = 0; jb < dg; jb += 32) {
        int cnt = min(32, dg - jb);
        int idx = (lane < cnt) ? __ldg(ssrc + rs + jb + lane) : 0;
        int j = 0;
        for (; j + 3 < cnt; j += 4) {
            int s0 = __shfl_sync(0xffffffffu, idx, j + half);
            int s1 = __shfl_sync(0xffffffffu, idx, j + 2 + half);
            uint4 v0 = __ldg((const uint4*)(xhp + (size_t)s0 * HH) + q);
            uint4 v1 = __ldg((const uint4*)(xhp + (size_t)s1 * HH) + q);
            ACC8(v0); ACC8(v1);
        }
        for (; j + 1 < cnt; j += 2) {
            int s0 = __shfl_sync(0xffffffffu, idx, j + half);
            uint4 v0 = __ldg((const uint4*)(xhp + (size_t)s0 * HH) + q);
            ACC8(v0);
        }
        if (j < cnt) {
            int s0 = __shfl_sync(0xffffffffu, idx, j);
            if (half == 0) {
                uint4 v0 = __ldg((const uint4*)(xhp + (size_t)s0 * HH) + q);
                ACC8(v0);
            }
        }
    }
    #undef ACC8

    #pragma unroll
    for (int k = 0; k < 8; ++k)
        a[k] += __shfl_down_sync(0xffffffffu, a[k], 16);

    if (lane < 16) {
        __nv_bfloat162 hp[4], lp[4];
        #pragma unroll
        for (int k = 0; k < 4; ++k) {
            bf16 h0 = __float2bfloat16(a[2 * k]);
            bf16 h1 = __float2bfloat16(a[2 * k + 1]);
            hp[k].x = h0; hp[k].y = h1;
            lp[k].x = __float2bfloat16(a[2 * k]     - __bfloat162float(h0));
            lp[k].y = __float2bfloat16(a[2 * k + 1] - __bfloat162float(h1));
        }
        uint4 hv, lv;
        hv.x = *(uint32_t*)&hp[0]; hv.y = *(uint32_t*)&hp[1];
        hv.z = *(uint32_t*)&hp[2]; hv.w = *(uint32_t*)&hp[3];
        lv.x = *(uint32_t*)&lp[0]; lv.y = *(uint32_t*)&lp[1];
        lv.z = *(uint32_t*)&lp[2]; lv.w = *(uint32_t*)&lp[3];
        *((uint4*)(oh + (size_t)warp * HH) + q) = hv;
        *((uint4*)(ol + (size_t)warp * HH) + q) = lv;
    }
}

// Layer-1 gather: reads bf16 xh (96B/row); half-warp per edge-parity,
// lanes hl<12 each load one uint2 (4 cols). 4-edge unrolled.
__global__ void conv_gather48(const bf16* __restrict__ xhp,
                              const int* __restrict__ rows, const int* __restrict__ deg,
                              const int* __restrict__ ssrc,
                              bf16* __restrict__ oh, bf16* __restrict__ ol, int N) {
    int warp = (blockIdx.x * blockDim.x + threadIdx.x) >> 5;
    int lane = threadIdx.x & 31;
    if (warp >= N) return;
    const int half = lane >> 4;
    const int hl   = lane & 15;
    const bool act = hl < 12;
    int rs = __ldg(rows + warp), dg = __ldg(deg + warp);
    float a0 = 0.f, a1 = 0.f, a2 = 0.f, a3 = 0.f;

    #define ACC4B(v) { \
        float2 p0 = __bfloat1622float2(*(__nv_bfloat162*)&(v).x); \
        float2 p1 = __bfloat1622float2(*(__nv_bfloat162*)&(v).y); \
        a0 += p0.x; a1 += p0.y; a2 += p1.x; a3 += p1.y; }

    for (int jb = 0; jb < dg; jb += 32) {
        int cnt = min(32, dg - jb);
        int idx = (lane < cnt) ? __ldg(ssrc + rs + jb + lane) : 0;
        int j = 0;
        for (; j + 7 < cnt; j += 8) {
            int sa = __shfl_sync(0xffffffffu, idx, j + half);
            int sb = __shfl_sync(0xffffffffu, idx, j + 2 + half);
            int sc = __shfl_sync(0xffffffffu, idx, j + 4 + half);
            int sd = __shfl_sync(0xffffffffu, idx, j + 6 + half);
            if (act) {
                uint2 v0 = __ldg((const uint2*)(xhp + (size_t)sa * D_IN) + hl);
                uint2 v1 = __ldg((const uint2*)(xhp + (size_t)sb * D_IN) + hl);
                uint2 v2 = __ldg((const uint2*)(xhp + (size_t)sc * D_IN) + hl);
                uint2 v3 = __ldg((const uint2*)(xhp + (size_t)sd * D_IN) + hl);
                ACC4B(v0); ACC4B(v1); ACC4B(v2); ACC4B(v3);
            }
        }
        for (; j + 1 < cnt; j += 2) {
            int sa = __shfl_sync(0xffffffffu, idx, j + half);
            if (act) {
                uint2 v0 = __ldg((const uint2*)(xhp + (size_t)sa * D_IN) + hl);
                ACC4B(v0);
            }
        }
        if (j < cnt) {
            int sa = __shfl_sync(0xffffffffu, idx, j);
            if (half == 0 && act) {
                uint2 v0 = __ldg((const uint2*)(xhp + (size_t)sa * D_IN) + hl);
                ACC4B(v0);
            }
        }
    }
    #undef ACC4B
    a0 += __shfl_down_sync(0xffffffffu, a0, 16);
    a1 += __shfl_down_sync(0xffffffffu, a1, 16);
    a2 += __shfl_down_sync(0xffffffffu, a2, 16);
    a3 += __shfl_down_sync(0xffffffffu, a3, 16);
    if (lane < 12) {
        bf16 hx = __float2bfloat16(a0), hy = __float2bfloat16(a1);
        bf16 hz = __float2bfloat16(a2), hw = __float2bfloat16(a3);
        __nv_bfloat162 hp0, hp1, lp0, lp1;
        hp0.x = hx; hp0.y = hy; hp1.x = hz; hp1.y = hw;
        lp0.x = __float2bfloat16(a0 - __bfloat162float(hx));
        lp0.y = __float2bfloat16(a1 - __bfloat162float(hy));
        lp1.x = __float2bfloat16(a2 - __bfloat162float(hz));
        lp1.y = __float2bfloat16(a3 - __bfloat162float(hw));
        uint2 hv, lv;
        hv.x = *(uint32_t*)&hp0; hv.y = *(uint32_t*)&hp1;
        lv.x = *(uint32_t*)&lp0; lv.y = *(uint32_t*)&lp1;
        *(uint2*)(oh + (size_t)warp * D_IN + lane * 4) = hv;
        *(uint2*)(ol + (size_t)warp * D_IN + lane * 4) = lv;
    }
}

// ---------------- launch ----------------
extern "C" void kernel_launch(void* const* d_in, const int* in_sizes, int n_in,
                              void* d_out, int out_size) {
    const float* x   = (const float*)d_in[0];
    const int*   ei  = (const int*)  d_in[1];
    const float* W1a = (const float*)d_in[2];
    const float* b1a = (const float*)d_in[3];
    const float* W1b = (const float*)d_in[4];
    const float* b1b = (const float*)d_in[5];
    const float* W2a = (const float*)d_in[6];
    const float* b2a = (const float*)d_in[7];
    const float* W2b = (const float*)d_in[8];
    const float* b2b = (const float*)d_in[9];
    const float* W3a = (const float*)d_in[10];
    const float* b3a = (const float*)d_in[11];
    const float* W3b = (const float*)d_in[12];
    const float* b3b = (const float*)d_in[13];
    float* out = (float*)d_out;

    const int N = in_sizes[0] / D_IN;
    const int E = in_sizes[1] / 2;
    const int* src = ei;
    const int* dst = ei + E;

    bf16 *xh, *xl, *c1h, *c1l, *cbh, *cbl, *th, *tl, *h1h, *h1l, *h2h, *h2l;
    bf16 *W1ah, *W1al, *W1bh, *W1bl, *W2ah, *W2al, *W2bh, *W2bl, *W3ah, *W3al, *W3bh, *W3bl;
    int *deg, *rows, *cursor, *bsum, *ssrc;
    cudaGetSymbolAddress((void**)&xh, g_xh);   cudaGetSymbolAddress((void**)&xl, g_xl);
    cudaGetSymbolAddress((void**)&c1h, g_c1h); cudaGetSymbolAddress((void**)&c1l, g_c1l);
    cudaGetSymbolAddress((void**)&cbh, g_cbh); cudaGetSymbolAddress((void**)&cbl, g_cbl);
    cudaGetSymbolAddress((void**)&th, g_th);   cudaGetSymbolAddress((void**)&tl, g_tl);
    cudaGetSymbolAddress((void**)&h1h, g_h1h); cudaGetSymbolAddress((void**)&h1l, g_h1l);
    cudaGetSymbolAddress((void**)&h2h, g_h2h); cudaGetSymbolAddress((void**)&h2l, g_h2l);
    cudaGetSymbolAddress((void**)&deg, g_deg); cudaGetSymbolAddress((void**)&rows, g_rows);
    cudaGetSymbolAddress((void**)&cursor, g_cursor);
    cudaGetSymbolAddress((void**)&bsum, g_bsum);
    cudaGetSymbolAddress((void**)&ssrc, g_ssrc);
    cudaGetSymbolAddress((void**)&W1ah, g_W1ah); cudaGetSymbolAddress((void**)&W1al, g_W1al);
    cudaGetSymbolAddress((void**)&W1bh, g_W1bh); cudaGetSymbolAddress((void**)&W1bl, g_W1bl);
    cudaGetSymbolAddress((void**)&W2ah, g_W2ah); cudaGetSymbolAddress((void**)&W2al, g_W2al);
    cudaGetSymbolAddress((void**)&W2bh, g_W2bh); cudaGetSymbolAddress((void**)&W2bl, g_W2bl);
    cudaGetSymbolAddress((void**)&W3ah, g_W3ah); cudaGetSymbolAddress((void**)&W3al, g_W3al);
    cudaGetSymbolAddress((void**)&W3bh, g_W3bh); cudaGetSymbolAddress((void**)&W3bl, g_W3bl);

    // stage = 2*A(8KB) + 2*B(NB*64B); 3 stages + 1KB alignment pad
    const int SZ128 = 1024 + 3 * (2 * 8192 + 2 * 8192);   // 99328
    const int SZ64  = 1024 + 3 * (2 * 8192 + 2 * 4096);   // 74752
    cudaFuncSetAttribute(gemm_mma<128, 0>, cudaFuncAttributeMaxDynamicSharedMemorySize, SZ128);
    cudaFuncSetAttribute(gemm_mma<64, 2>,  cudaFuncAttributeMaxDynamicSharedMemorySize, SZ64);

    const int mb = (N + 127) / 128;
    const int nwarp_blocks = (N * 32 + 255) / 256;

    // ---- zero deg, then fused prologue (x split + weight splits + hist) ----
    zero_deg_kernel<<<(N / 4 + 255) / 256, 256>>>(deg, N / 4);   // N multiple of 4
    prep_kernel<<<2048, 256>>>(x, xh, xl, N * D_IN, dst, E, deg,
                               W1a, W1ah, W1al, W1b, W1bh, W1bl,
                               W2a, W2ah, W2al, W2b, W2bh, W2bl,
                               W3a, W3ah, W3al, W3b, W3bh, W3bl);

    // ---- CSR build (once; reused by all 3 convs) ----
    const int nb = (N + 1023) / 1024;
    scan1_kernel<<<nb, 1024>>>(deg, rows, bsum, N);
    scan23_kernel<<<(N + 255) / 256, 256>>>(rows, cursor, bsum, N, nb);
    permute_kernel<<<(E / 4 + 255) / 256, 256>>>(src, dst, cursor, ssrc, E);

    // ---- layer 1 ----
    conv_gather48<<<nwarp_blocks, 256>>>(xh, rows, deg, ssrc, c1h, c1l, N);
    gemm_mma<128, 0><<<dim3(2, mb), 256, SZ128>>>(c1h, c1l, D_IN, xh, xl, D_IN,
        nullptr, nullptr, 0, 96, W1ah, W1al, b1a, nullptr, th, tl, N, HID);
    gemm_mma<128, 0><<<dim3(1, mb), 256, SZ128>>>(th, tl, HID, nullptr, nullptr, 0,
        nullptr, nullptr, 0, HID, W1bh, W1bl, b1b, nullptr, h1h, h1l, N, HH);

    // ---- layer 2 ----
    conv_gather128_bf<<<nwarp_blocks, 256>>>(h1h, rows, deg, ssrc, cbh, cbl, N);
    gemm_mma<128, 0><<<dim3(2, mb), 256, SZ128>>>(cbh, cbl, HH, h1h, h1l, HH,
        xh, xl, D_IN, 304, W2ah, W2al, b2a, nullptr, th, tl, N, HID);
    gemm_mma<128, 0><<<dim3(1, mb), 256, SZ128>>>(th, tl, HID, nullptr, nullptr, 0,
        nullptr, nullptr, 0, HID, W2bh, W2bl, b2b, nullptr, h2h, h2l, N, HH);

    // ---- layer 3 ----
    conv_gather128_bf<<<nwarp_blocks, 256>>>(h2h, rows, deg, ssrc, cbh, cbl, N);
    gemm_mma<128, 0><<<dim3(2, mb), 256, SZ128>>>(cbh, cbl, HH, h2h, h2l, HH,
        xh, xl, D_IN, 304, W3ah, W3al, b3a, nullptr, th, tl, N, HID);
    gemm_mma<64, 2><<<dim3(1, mb), 256, SZ64>>>(th, tl, HID, nullptr, nullptr, 0,
        nullptr, nullptr, 0, HID, W3bh, W3bl, b3b, out, nullptr, nullptr, N, NOUT);
}

// round 17
// speedup vs baseline: 1.0045x; 1.0045x over previous
#include <cuda_runtime.h>
#include <cuda_bf16.h>
#include <math.h>
#include <stdint.h>

#define MAXN 100000
#define MAXE 1600000
#define D_IN 48
#define HID 256
#define HH 128
#define NOUT 40

typedef __nv_bfloat16 bf16;

// ---------------- scratch (device globals; no allocation allowed) ----------
__device__ __align__(256) bf16 g_xh [(size_t)MAXN * D_IN], g_xl [(size_t)MAXN * D_IN];
__device__ __align__(256) bf16 g_c1h[(size_t)MAXN * D_IN], g_c1l[(size_t)MAXN * D_IN];
__device__ __align__(256) bf16 g_cbh[(size_t)MAXN * HH],  g_cbl[(size_t)MAXN * HH];
__device__ __align__(256) bf16 g_th [(size_t)MAXN * HID], g_tl [(size_t)MAXN * HID];
__device__ __align__(256) bf16 g_h1h[(size_t)MAXN * HH],  g_h1l[(size_t)MAXN * HH];
__device__ __align__(256) bf16 g_h2h[(size_t)MAXN * HH],  g_h2l[(size_t)MAXN * HH];
// CSR
__device__ __align__(256) int g_deg[MAXN];
__device__ __align__(256) int g_rows[MAXN];
__device__ __align__(256) int g_cursor[MAXN];
__device__ __align__(256) int g_bsum[128];
__device__ __align__(256) int g_ssrc[MAXE];
// weights, transposed to [Npad, K] and hi/lo split
__device__ __align__(256) bf16 g_W1ah[256*96],  g_W1al[256*96];
__device__ __align__(256) bf16 g_W1bh[128*256], g_W1bl[128*256];
__device__ __align__(256) bf16 g_W2ah[256*304], g_W2al[256*304];
__device__ __align__(256) bf16 g_W2bh[128*256], g_W2bl[128*256];
__device__ __align__(256) bf16 g_W3ah[256*304], g_W3al[256*304];
__device__ __align__(256) bf16 g_W3bh[64*256],  g_W3bl[64*256];

// ---------------- PTX helpers (family-common: sm_80-era only) --------------
__device__ __forceinline__ uint32_t sm_u32(const void* p) {
    uint32_t a;
    asm("{ .reg .u64 t; cvta.to.shared.u64 t, %1; cvt.u32.u64 %0, t; }" : "=r"(a) : "l"(p));
    return a;
}
__device__ __forceinline__ void cp16(uint32_t dst, const void* src, bool ok) {
    int sz = ok ? 16 : 0;
    asm volatile("cp.async.cg.shared.global [%0], [%1], 16, %2;"
                 :: "r"(dst), "l"(src), "r"(sz) : "memory");
}
__device__ __forceinline__ void cp_commit() {
    asm volatile("cp.async.commit_group;" ::: "memory");
}
__device__ __forceinline__ void ldsm4(uint32_t& r0, uint32_t& r1, uint32_t& r2, uint32_t& r3,
                                      uint32_t a) {
    asm volatile("ldmatrix.sync.aligned.m8n8.x4.shared.b16 {%0,%1,%2,%3}, [%4];"
                 : "=r"(r0), "=r"(r1), "=r"(r2), "=r"(r3) : "r"(a));
}
__device__ __forceinline__ void mma16816(float* c, const uint32_t* a, const uint32_t* b) {
    asm volatile("mma.sync.aligned.m16n8k16.row.col.f32.bf16.bf16.f32 "
                 "{%0,%1,%2,%3}, {%4,%5,%6,%7}, {%8,%9}, {%0,%1,%2,%3};"
                 : "+f"(c[0]), "+f"(c[1]), "+f"(c[2]), "+f"(c[3])
                 : "r"(a[0]), "r"(a[1]), "r"(a[2]), "r"(a[3]), "r"(b[0]), "r"(b[1]));
}

// ---------------- fused 3-pass mma.sync GEMM (round-9 frozen config) -------
// Per k-tile stage holds {Ahi, Alo, Bh, Bl}; issues Ahi*Bh + Ahi*Bl + Alo*Bh
// into the same fp32 accumulators. BM=128, BK=32, 3-stage cp.async pipeline.
// MODE 0: relu -> bf16 hi/lo
// MODE 2: log_softmax (first 40 cols) -> fp32, row stride 40
template<int NB, int MODE>
__global__ __launch_bounds__(256)
void gemm_mma(const bf16* __restrict__ a0h, const bf16* __restrict__ a0l, int w0,
              const bf16* __restrict__ a1h, const bf16* __restrict__ a1l, int w1,
              const bf16* __restrict__ a2h, const bf16* __restrict__ a2l, int w2,
              int Kp,
              const bf16* __restrict__ Bh, const bf16* __restrict__ Bl,
              const float* __restrict__ bias,
              float* __restrict__ outF, bf16* __restrict__ outHi, bf16* __restrict__ outLo,
              int M, int ldo) {
    extern __shared__ char dyn[];
    constexpr int ASZ = 128 * 64;
    constexpr int BSZ = NB * 64;
    constexpr int STG = 2 * ASZ + 2 * BSZ;
    constexpr int WM  = (NB == 128) ? 2 : 4;
    constexpr int MF  = (128 / WM) / 16;
    constexpr int NF  = 4;

    const uint32_t raw  = sm_u32(dyn);
    const uint32_t base = (raw + 1023u) & ~1023u;
    const int tid  = threadIdx.x;
    const int w    = tid >> 5;
    const int lane = tid & 31;
    const int blockM = blockIdx.y * 128;
    const int blockN = blockIdx.x * NB;
    const int wm = (NB == 128) ? (w >> 2) : (w >> 1);
    const int wn = (NB == 128) ? (w & 3)  : (w & 1);
    const int wmBase = wm * (128 / WM);
    const int nBase  = wn * 32;

    const int KT  = (Kp + 31) >> 5;
    const int w01 = w0 + w1;

    const int r8 = lane & 7, mi = lane >> 3;
    uint32_t addrA[MF][2], addrB[NF / 2][2];
    #pragma unroll
    for (int i = 0; i < MF; ++i) {
        int row = wmBase + i * 16 + ((mi & 1) << 3) + r8;
        int s   = (row >> 1) & 3;
        #pragma unroll
        for (int ks = 0; ks < 2; ++ks) {
            int c = (ks << 1) + (mi >> 1);
            addrA[i][ks] = base + row * 64 + ((c ^ s) << 4);
        }
    }
    #pragma unroll
    for (int jp = 0; jp < NF / 2; ++jp) {
        int row = nBase + jp * 16 + ((mi >> 1) << 3) + r8;
        int s   = (row >> 1) & 3;
        #pragma unroll
        for (int ks = 0; ks < 2; ++ks) {
            int c = (ks << 1) + (mi & 1);
            addrB[jp][ks] = base + 2 * ASZ + row * 64 + ((c ^ s) << 4);
        }
    }

    float acc[MF][NF][4];
    #pragma unroll
    for (int i = 0; i < MF; ++i)
        #pragma unroll
        for (int j = 0; j < NF; ++j)
            #pragma unroll
            for (int q = 0; q < 4; ++q) acc[i][j][q] = 0.f;

    auto load_tile = [&](int t) {
        const int kb = t * 32;
        const uint32_t sAh = base + (t % 3) * STG;
        const uint32_t sAl = sAh + ASZ;
        const uint32_t sBh = sAh + 2 * ASZ;
        const uint32_t sBl = sBh + BSZ;
        #pragma unroll
        for (int i = 0; i < 2; ++i) {
            int id  = tid + i * 256;
            int row = id >> 2, ch = id & 3;
            int kk  = kb + ch * 8;
            int m   = blockM + row;
            bool ok = (m < M) && (kk < Kp);
            const bf16 *gh = a0h, *gl = a0l; int ld = w0, off = kk;
            if (kk < w0)       { gh = a0h; gl = a0l; ld = w0; off = kk; }
            else if (kk < w01) { gh = a1h; gl = a1l; ld = w1; off = kk - w0; }
            else               { gh = a2h; gl = a2l; ld = w2; off = kk - w01; }
            int sw = ch ^ ((row >> 1) & 3);
            cp16(sAh + row * 64 + (sw << 4),
                 ok ? (const void*)(gh + (size_t)m * ld + off) : (const void*)a0h, ok);
            cp16(sAl + row * 64 + (sw << 4),
                 ok ? (const void*)(gl + (size_t)m * ld + off) : (const void*)a0h, ok);
        }
        #pragma unroll
        for (int i = 0; i < NB / 64; ++i) {
            int id  = tid + i * 256;
            int row = id >> 2, ch = id & 3;
            int kk  = kb + ch * 8;
            bool ok = (kk < Kp);
            int sw = ch ^ ((row >> 1) & 3);
            cp16(sBh + row * 64 + (sw << 4),
                 ok ? (const void*)(Bh + (size_t)(blockN + row) * Kp + kk) : (const void*)Bh, ok);
            cp16(sBl + row * 64 + (sw << 4),
                 ok ? (const void*)(Bl + (size_t)(blockN + row) * Kp + kk) : (const void*)Bl, ok);
        }
        cp_commit();
    };

    load_tile(0);
    if (KT > 1) load_tile(1);

    for (int t = 0; t < KT; ++t) {
        if (t + 2 <= KT) asm volatile("cp.async.wait_group 1;" ::: "memory");
        else             asm volatile("cp.async.wait_group 0;" ::: "memory");
        __syncthreads();
        if (t + 2 < KT) load_tile(t + 2);

        const uint32_t stOff = (t % 3) * STG;
        #pragma unroll
        for (int ks = 0; ks < 2; ++ks) {
            uint32_t ah[MF][4], al[MF][4], bh[NF][2], bl[NF][2];
            #pragma unroll
            for (int jp = 0; jp < NF / 2; ++jp)
                ldsm4(bh[jp*2][0], bh[jp*2][1], bh[jp*2+1][0], bh[jp*2+1][1],
                      addrB[jp][ks] + stOff);
            #pragma unroll
            for (int i = 0; i < MF; ++i)
                ldsm4(ah[i][0], ah[i][1], ah[i][2], ah[i][3], addrA[i][ks] + stOff);
            #pragma unroll
            for (int i = 0; i < MF; ++i)
                #pragma unroll
                for (int j = 0; j < NF; ++j)
                    mma16816(acc[i][j], ah[i], bh[j]);
            #pragma unroll
            for (int jp = 0; jp < NF / 2; ++jp)
                ldsm4(bl[jp*2][0], bl[jp*2][1], bl[jp*2+1][0], bl[jp*2+1][1],
                      addrB[jp][ks] + stOff + BSZ);
            #pragma unroll
            for (int i = 0; i < MF; ++i)
                #pragma unroll
                for (int j = 0; j < NF; ++j)
                    mma16816(acc[i][j], ah[i], bl[j]);
            #pragma unroll
            for (int i = 0; i < MF; ++i)
                ldsm4(al[i][0], al[i][1], al[i][2], al[i][3], addrA[i][ks] + stOff + ASZ);
            #pragma unroll
            for (int i = 0; i < MF; ++i)
                #pragma unroll
                for (int j = 0; j < NF; ++j)
                    mma16816(acc[i][j], al[i], bh[j]);
        }
    }

    const int g4 = lane >> 2, t2 = lane & 3;
    if (MODE == 2) {
        __syncthreads();
        float* sl = (float*)(dyn + (base - raw));
        #pragma unroll
        for (int i = 0; i < MF; ++i) {
            int rl = wmBase + i * 16 + g4;
            #pragma unroll
            for (int j = 0; j < NF; ++j) {
                int col = nBase + j * 8 + t2 * 2;
                float b0 = (col < NOUT) ? __ldg(bias + col) : 0.f;
                float b1 = (col + 1 < NOUT) ? __ldg(bias + col + 1) : 0.f;
                sl[rl * 65 + col]           = acc[i][j][0] + b0;
                sl[rl * 65 + col + 1]       = acc[i][j][1] + b1;
                sl[(rl + 8) * 65 + col]     = acc[i][j][2] + b0;
                sl[(rl + 8) * 65 + col + 1] = acc[i][j][3] + b1;
            }
        }
        __syncthreads();
        if (tid < 128) {
            int m = blockM + tid;
            if (m < M) {
                const float* r = sl + tid * 65;
                float mx = -INFINITY;
                #pragma unroll
                for (int c = 0; c < NOUT; ++c) mx = fmaxf(mx, r[c]);
                float s = 0.f;
                #pragma unroll
                for (int c = 0; c < NOUT; ++c) s += expf(r[c] - mx);
                float lse = mx + logf(s);
                #pragma unroll
                for (int c = 0; c < NOUT; ++c) outF[(size_t)m * NOUT + c] = r[c] - lse;
            }
        }
    } else {
        #pragma unroll
        for (int i = 0; i < MF; ++i) {
            int r0 = blockM + wmBase + i * 16 + g4;
            #pragma unroll
            for (int j = 0; j < NF; ++j) {
                int colg = blockN + nBase + j * 8 + t2 * 2;
                float b0 = __ldg(bias + colg), b1 = __ldg(bias + colg + 1);
                #pragma unroll
                for (int h = 0; h < 2; ++h) {
                    int m = r0 + h * 8;
                    if (m < M) {
                        float v0 = fmaxf(acc[i][j][h * 2 + 0] + b0, 0.f);
                        float v1 = fmaxf(acc[i][j][h * 2 + 1] + b1, 0.f);
                        bf16 h0 = __float2bfloat16(v0);
                        bf16 h1 = __float2bfloat16(v1);
                        __nv_bfloat162 hp; hp.x = h0; hp.y = h1;
                        __nv_bfloat162 lp;
                        lp.x = __float2bfloat16(v0 - __bfloat162float(h0));
                        lp.y = __float2bfloat16(v1 - __bfloat162float(h1));
                        *(__nv_bfloat162*)(outHi + (size_t)m * ldo + colg) = hp;
                        *(__nv_bfloat162*)(outLo + (size_t)m * ldo + colg) = lp;
                    }
                }
            }
        }
    }
}

// ---------------- fused elementwise prologue + histogram -------------------
__device__ __forceinline__ void wsplit_one(const float* __restrict__ W, int K, int Nn,
                                           int i, bf16* __restrict__ bh,
                                           bf16* __restrict__ bl) {
    int n = i / K, k = i - n * K;
    float v = (n < Nn) ? W[(size_t)k * Nn + n] : 0.f;
    bf16 h = __float2bfloat16(v);
    bh[i] = h;
    bl[i] = __float2bfloat16(v - __bfloat162float(h));
}

__global__ void zero_deg_kernel(int* __restrict__ deg, int n4) {
    int i = blockIdx.x * blockDim.x + threadIdx.x;
    if (i < n4) ((int4*)deg)[i] = make_int4(0, 0, 0, 0);
}

// prep: x split + 6 weight splits + degree histogram (deg pre-zeroed)
__global__ void prep_kernel(const float* __restrict__ x, bf16* __restrict__ xh,
                            bf16* __restrict__ xl, int nx,
                            const int* __restrict__ dst, int E, int* __restrict__ deg,
                            const float* W1a, bf16* W1ah, bf16* W1al,
                            const float* W1b, bf16* W1bh, bf16* W1bl,
                            const float* W2a, bf16* W2ah, bf16* W2al,
                            const float* W2b, bf16* W2bh, bf16* W2bl,
                            const float* W3a, bf16* W3ah, bf16* W3al,
                            const float* W3b, bf16* W3bh, bf16* W3bl) {
    const int C1 = 256 * 96, C2 = 128 * 256, C3 = 256 * 304, C6 = 64 * 256;
    const int S1 = nx;
    const int E1 = S1 + C1, E2 = E1 + C2, E3 = E2 + C3;
    const int E4 = E3 + C2, E5 = E4 + C3, E6 = E5 + C6;
    const int H  = (E + 3) >> 2;
    const int E7 = E6 + H;
    int i  = blockIdx.x * blockDim.x + threadIdx.x;
    int st = gridDim.x * blockDim.x;
    for (; i < E7; i += st) {
        if (i < S1) {
            float v = x[i];
            bf16 h = __float2bfloat16(v);
            xh[i] = h;
            xl[i] = __float2bfloat16(v - __bfloat162float(h));
        }
        else if (i < E1) wsplit_one(W1a, 96, 256, i - S1, W1ah, W1al);
        else if (i < E2) wsplit_one(W1b, 256, 128, i - E1, W1bh, W1bl);
        else if (i < E3) wsplit_one(W2a, 304, 256, i - E2, W2ah, W2al);
        else if (i < E4) wsplit_one(W2b, 256, 128, i - E3, W2bh, W2bl);
        else if (i < E5) wsplit_one(W3a, 304, 256, i - E4, W3ah, W3al);
        else if (i < E6) wsplit_one(W3b, 256, NOUT, i - E5, W3bh, W3bl);
        else {
            int b = (i - E6) * 4;
            if (b + 3 < E) {
                int4 d4 = __ldg((const int4*)(dst + b));
                atomicAdd(deg + d4.x, 1);
                atomicAdd(deg + d4.y, 1);
                atomicAdd(deg + d4.z, 1);
                atomicAdd(deg + d4.w, 1);
            } else {
                for (int e = b; e < E; ++e) atomicAdd(deg + __ldg(dst + e), 1);
            }
        }
    }
}

// ---------------- CSR build ----------------
// 1024-thread block scan via warp shuffles (2 syncthreads total)
__global__ void scan1_kernel(const int* __restrict__ deg, int* __restrict__ rows,
                             int* __restrict__ bsum, int n) {
    __shared__ int wsum[32];
    int gid = blockIdx.x * 1024 + threadIdx.x;
    int lane = threadIdx.x & 31;
    int wid  = threadIdx.x >> 5;
    int v = (gid < n) ? deg[gid] : 0;
    int s = v;
    #pragma unroll
    for (int o = 1; o < 32; o <<= 1) {
        int t = __shfl_up_sync(0xffffffffu, s, o);
        if (lane >= o) s += t;
    }
    if (lane == 31) wsum[wid] = s;
    __syncthreads();
    if (wid == 0) {
        int ws = wsum[lane];
        #pragma unroll
        for (int o = 1; o < 32; o <<= 1) {
            int t = __shfl_up_sync(0xffffffffu, ws, o);
            if (lane >= o) ws += t;
        }
        wsum[lane] = ws;
        if (lane == 31 && blockIdx.x < 128) bsum[blockIdx.x] = ws;
    }
    __syncthreads();
    int excl = s - v + (wid > 0 ? wsum[wid - 1] : 0);
    if (gid < n) rows[gid] = excl;
}
// fused scan2+scan3: each block re-scans bsum locally (nb <= 128)
__global__ void scan23_kernel(int* __restrict__ rows, int* __restrict__ cursor,
                              const int* __restrict__ bsum, int n, int nb) {
    __shared__ int sh[128];
    int i = threadIdx.x;
    int v = 0;
    if (i < 128) {
        v = (i < nb) ? bsum[i] : 0;
        sh[i] = v;
    }
    __syncthreads();
    #pragma unroll
    for (int o = 1; o < 128; o <<= 1) {
        int t = (i < 128 && i >= o) ? sh[i - o] : 0;
        __syncthreads();
        if (i < 128) sh[i] += t;
        __syncthreads();
    }
    if (i < 128) sh[i] -= v;          // exclusive prefix
    __syncthreads();
    int gid = blockIdx.x * blockDim.x + threadIdx.x;
    if (gid < n) {
        int r = rows[gid] + sh[gid >> 10];
        rows[gid] = r;
        cursor[gid] = r;
    }
}
// 4 edges per thread, int4 index loads
__global__ void permute_kernel(const int* __restrict__ src, const int* __restrict__ dst,
                               int* __restrict__ cursor, int* __restrict__ ssrc, int E) {
    int t = blockIdx.x * blockDim.x + threadIdx.x;
    int b = t * 4;
    if (b + 3 < E) {
        int4 d4 = __ldg((const int4*)(dst + b));
        int4 s4 = __ldg((const int4*)(src + b));
        ssrc[atomicAdd(cursor + d4.x, 1)] = s4.x;
        ssrc[atomicAdd(cursor + d4.y, 1)] = s4.y;
        ssrc[atomicAdd(cursor + d4.z, 1)] = s4.z;
        ssrc[atomicAdd(cursor + d4.w, 1)] = s4.w;
    } else {
        for (int e = b; e < E; ++e) {
            int d = __ldg(dst + e);
            ssrc[atomicAdd(cursor + d, 1)] = __ldg(src + e);
        }
    }
}

// ---------------- gather-sum convs ----------------
// Layer-2/3 gather: reads HI array only (bf16-quantized conv input; error
// ~2^-10/sqrt(deg), well under tolerance). Lanes 0-15 even edges, 16-31 odd;
// each lane loads one uint4 (8 cols) -> 256B/edge. Merge via shfl_down(16).
__global__ void conv_gather128_bf(const bf16* __restrict__ xhp,
                                  const int* __restrict__ rows, const int* __restrict__ deg,
                                  const int* __restrict__ ssrc,
                                  bf16* __restrict__ oh, bf16* __restrict__ ol, int N) {
    int warp = (blockIdx.x * blockDim.x + threadIdx.x) >> 5;
    int lane = threadIdx.x & 31;
    if (warp >= N) return;
    const int half = lane >> 4;
    const int q    = lane & 15;
    int rs = __ldg(rows + warp), dg = __ldg(deg + warp);
    float a[8];
    #pragma unroll
    for (int k = 0; k < 8; ++k) a[k] = 0.f;

    #define ACC8(v) { \
        float2 p0 = __bfloat1622float2(*(__nv_bfloat162*)&(v).x); \
        float2 p1 = __bfloat1622float2(*(__nv_bfloat162*)&(v).y); \
        float2 p2 = __bfloat1622float2(*(__nv_bfloat162*)&(v).z); \
        float2 p3 = __bfloat1622float2(*(__nv_bfloat162*)&(v).w); \
        a[0] += p0.x; a[1] += p0.y; a[2] += p1.x; a[3] += p1.y; \
        a[4] += p2.x; a[5] += p2.y; a[6] += p3.x; a[7] += p3.y; }

    for (int jb = 0; jb < dg; jb += 32) {
        int cnt = min(32, dg - jb);
        int idx = (lane < cnt) ? __ldg(ssrc + rs + jb + lane) : 0;
        int j = 0;
        for (; j + 3 < cnt; j += 4) {
            int s0 = __shfl_sync(0xffffffffu, idx, j + half);
            int s1 = __shfl_sync(0xffffffffu, idx, j + 2 + half);
            uint4 v0 = __ldg((const uint4*)(xhp + (size_t)s0 * HH) + q);
            uint4 v1 = __ldg((const uint4*)(xhp + (size_t)s1 * HH) + q);
            ACC8(v0); ACC8(v1);
        }
        for (; j + 1 < cnt; j += 2) {
            int s0 = __shfl_sync(0xffffffffu, idx, j + half);
            uint4 v0 = __ldg((const uint4*)(xhp + (size_t)s0 * HH) + q);
            ACC8(v0);
        }
        if (j < cnt) {
            int s0 = __shfl_sync(0xffffffffu, idx, j);
            if (half == 0) {
                uint4 v0 = __ldg((const uint4*)(xhp + (size_t)s0 * HH) + q);
                ACC8(v0);
            }
        }
    }
    #undef ACC8

    #pragma unroll
    for (int k = 0; k < 8; ++k)
        a[k] += __shfl_down_sync(0xffffffffu, a[k], 16);

    if (lane < 16) {
        __nv_bfloat162 hp[4], lp[4];
        #pragma unroll
        for (int k = 0; k < 4; ++k) {
            bf16 h0 = __float2bfloat16(a[2 * k]);
            bf16 h1 = __float2bfloat16(a[2 * k + 1]);
            hp[k].x = h0; hp[k].y = h1;
            lp[k].x = __float2bfloat16(a[2 * k]     - __bfloat162float(h0));
            lp[k].y = __float2bfloat16(a[2 * k + 1] - __bfloat162float(h1));
        }
        uint4 hv, lv;
        hv.x = *(uint32_t*)&hp[0]; hv.y = *(uint32_t*)&hp[1];
        hv.z = *(uint32_t*)&hp[2]; hv.w = *(uint32_t*)&hp[3];
        lv.x = *(uint32_t*)&lp[0]; lv.y = *(uint32_t*)&lp[1];
        lv.z = *(uint32_t*)&lp[2]; lv.w = *(uint32_t*)&lp[3];
        *((uint4*)(oh + (size_t)warp * HH) + q) = hv;
        *((uint4*)(ol + (size_t)warp * HH) + q) = lv;
    }
}

// Layer-1 gather: reads bf16 xh (96B/row); half-warp per edge-parity,
// lanes hl<12 each load one uint2 (4 cols). (round-15 2-edge form)
__global__ void conv_gather48(const bf16* __restrict__ xhp,
                              const int* __restrict__ rows, const int* __restrict__ deg,
                              const int* __restrict__ ssrc,
                              bf16* __restrict__ oh, bf16* __restrict__ ol, int N) {
    int warp = (blockIdx.x * blockDim.x + threadIdx.x) >> 5;
    int lane = threadIdx.x & 31;
    if (warp >= N) return;
    const int half = lane >> 4;
    const int hl   = lane & 15;
    const bool act = hl < 12;
    int rs = __ldg(rows + warp), dg = __ldg(deg + warp);
    float a0 = 0.f, a1 = 0.f, a2 = 0.f, a3 = 0.f;

    #define ACC4B(v) { \
        float2 p0 = __bfloat1622float2(*(__nv_bfloat162*)&(v).x); \
        float2 p1 = __bfloat1622float2(*(__nv_bfloat162*)&(v).y); \
        a0 += p0.x; a1 += p0.y; a2 += p1.x; a3 += p1.y; }

    for (int jb = 0; jb < dg; jb += 32) {
        int cnt = min(32, dg - jb);
        int idx = (lane < cnt) ? __ldg(ssrc + rs + jb + lane) : 0;
        int j = 0;
        for (; j + 3 < cnt; j += 4) {
            int sa = __shfl_sync(0xffffffffu, idx, j + half);
            int sb = __shfl_sync(0xffffffffu, idx, j + 2 + half);
            if (act) {
                uint2 v0 = __ldg((const uint2*)(xhp + (size_t)sa * D_IN) + hl);
                uint2 v1 = __ldg((const uint2*)(xhp + (size_t)sb * D_IN) + hl);
                ACC4B(v0); ACC4B(v1);
            }
        }
        for (; j + 1 < cnt; j += 2) {
            int sa = __shfl_sync(0xffffffffu, idx, j + half);
            if (act) {
                uint2 v0 = __ldg((const uint2*)(xhp + (size_t)sa * D_IN) + hl);
                ACC4B(v0);
            }
        }
        if (j < cnt) {
            int sa = __shfl_sync(0xffffffffu, idx, j);
            if (half == 0 && act) {
                uint2 v0 = __ldg((const uint2*)(xhp + (size_t)sa * D_IN) + hl);
                ACC4B(v0);
            }
        }
    }
    #undef ACC4B
    a0 += __shfl_down_sync(0xffffffffu, a0, 16);
    a1 += __shfl_down_sync(0xffffffffu, a1, 16);
    a2 += __shfl_down_sync(0xffffffffu, a2, 16);
    a3 += __shfl_down_sync(0xffffffffu, a3, 16);
    if (lane < 12) {
        bf16 hx = __float2bfloat16(a0), hy = __float2bfloat16(a1);
        bf16 hz = __float2bfloat16(a2), hw = __float2bfloat16(a3);
        __nv_bfloat162 hp0, hp1, lp0, lp1;
        hp0.x = hx; hp0.y = hy; hp1.x = hz; hp1.y = hw;
        lp0.x = __float2bfloat16(a0 - __bfloat162float(hx));
        lp0.y = __float2bfloat16(a1 - __bfloat162float(hy));
        lp1.x = __float2bfloat16(a2 - __bfloat162float(hz));
        lp1.y = __float2bfloat16(a3 - __bfloat162float(hw));
        uint2 hv, lv;
        hv.x = *(uint32_t*)&hp0; hv.y = *(uint32_t*)&hp1;
        lv.x = *(uint32_t*)&lp0; lv.y = *(uint32_t*)&lp1;
        *(uint2*)(oh + (size_t)warp * D_IN + lane * 4) = hv;
        *(uint2*)(ol + (size_t)warp * D_IN + lane * 4) = lv;
    }
}

// ---------------- launch ----------------
extern "C" void kernel_launch(void* const* d_in, const int* in_sizes, int n_in,
                              void* d_out, int out_size) {
    const float* x   = (const float*)d_in[0];
    const int*   ei  = (const int*)  d_in[1];
    const float* W1a = (const float*)d_in[2];
    const float* b1a = (const float*)d_in[3];
    const float* W1b = (const float*)d_in[4];
    const float* b1b = (const float*)d_in[5];
    const float* W2a = (const float*)d_in[6];
    const float* b2a = (const float*)d_in[7];
    const float* W2b = (const float*)d_in[8];
    const float* b2b = (const float*)d_in[9];
    const float* W3a = (const float*)d_in[10];
    const float* b3a = (const float*)d_in[11];
    const float* W3b = (const float*)d_in[12];
    const float* b3b = (const float*)d_in[13];
    float* out = (float*)d_out;

    const int N = in_sizes[0] / D_IN;
    const int E = in_sizes[1] / 2;
    const int* src = ei;
    const int* dst = ei + E;

    bf16 *xh, *xl, *c1h, *c1l, *cbh, *cbl, *th, *tl, *h1h, *h1l, *h2h, *h2l;
    bf16 *W1ah, *W1al, *W1bh, *W1bl, *W2ah, *W2al, *W2bh, *W2bl, *W3ah, *W3al, *W3bh, *W3bl;
    int *deg, *rows, *cursor, *bsum, *ssrc;
    cudaGetSymbolAddress((void**)&xh, g_xh);   cudaGetSymbolAddress((void**)&xl, g_xl);
    cudaGetSymbolAddress((void**)&c1h, g_c1h); cudaGetSymbolAddress((void**)&c1l, g_c1l);
    cudaGetSymbolAddress((void**)&cbh, g_cbh); cudaGetSymbolAddress((void**)&cbl, g_cbl);
    cudaGetSymbolAddress((void**)&th, g_th);   cudaGetSymbolAddress((void**)&tl, g_tl);
    cudaGetSymbolAddress((void**)&h1h, g_h1h); cudaGetSymbolAddress((void**)&h1l, g_h1l);
    cudaGetSymbolAddress((void**)&h2h, g_h2h); cudaGetSymbolAddress((void**)&h2l, g_h2l);
    cudaGetSymbolAddress((void**)&deg, g_deg); cudaGetSymbolAddress((void**)&rows, g_rows);
    cudaGetSymbolAddress((void**)&cursor, g_cursor);
    cudaGetSymbolAddress((void**)&bsum, g_bsum);
    cudaGetSymbolAddress((void**)&ssrc, g_ssrc);
    cudaGetSymbolAddress((void**)&W1ah, g_W1ah); cudaGetSymbolAddress((void**)&W1al, g_W1al);
    cudaGetSymbolAddress((void**)&W1bh, g_W1bh); cudaGetSymbolAddress((void**)&W1bl, g_W1bl);
    cudaGetSymbolAddress((void**)&W2ah, g_W2ah); cudaGetSymbolAddress((void**)&W2al, g_W2al);
    cudaGetSymbolAddress((void**)&W2bh, g_W2bh); cudaGetSymbolAddress((void**)&W2bl, g_W2bl);
    cudaGetSymbolAddress((void**)&W3ah, g_W3ah); cudaGetSymbolAddress((void**)&W3al, g_W3al);
    cudaGetSymbolAddress((void**)&W3bh, g_W3bh); cudaGetSymbolAddress((void**)&W3bl, g_W3bl);

    // stage = 2*A(8KB) + 2*B(NB*64B); 3 stages + 1KB alignment pad
    const int SZ128 = 1024 + 3 * (2 * 8192 + 2 * 8192);   // 99328
    const int SZ64  = 1024 + 3 * (2 * 8192 + 2 * 4096);   // 74752
    cudaFuncSetAttribute(gemm_mma<128, 0>, cudaFuncAttributeMaxDynamicSharedMemorySize, SZ128);
    cudaFuncSetAttribute(gemm_mma<64, 2>,  cudaFuncAttributeMaxDynamicSharedMemorySize, SZ64);

    const int mb = (N + 127) / 128;
    const int nwarp_blocks = (N * 32 + 255) / 256;

    // ---- zero deg, then fused prologue (x split + weight splits + hist) ----
    zero_deg_kernel<<<(N / 4 + 255) / 256, 256>>>(deg, N / 4);   // N multiple of 4
    prep_kernel<<<2048, 256>>>(x, xh, xl, N * D_IN, dst, E, deg,
                               W1a, W1ah, W1al, W1b, W1bh, W1bl,
                               W2a, W2ah, W2al, W2b, W2bh, W2bl,
                               W3a, W3ah, W3al, W3b, W3bh, W3bl);

    // ---- CSR build (once; reused by all 3 convs) ----
    const int nb = (N + 1023) / 1024;
    scan1_kernel<<<nb, 1024>>>(deg, rows, bsum, N);
    scan23_kernel<<<(N + 255) / 256, 256>>>(rows, cursor, bsum, N, nb);
    permute_kernel<<<(E / 4 + 255) / 256, 256>>>(src, dst, cursor, ssrc, E);

    // ---- layer 1 ----
    conv_gather48<<<nwarp_blocks, 256>>>(xh, rows, deg, ssrc, c1h, c1l, N);
    gemm_mma<128, 0><<<dim3(2, mb), 256, SZ128>>>(c1h, c1l, D_IN, xh, xl, D_IN,
        nullptr, nullptr, 0, 96, W1ah, W1al, b1a, nullptr, th, tl, N, HID);
    gemm_mma<128, 0><<<dim3(1, mb), 256, SZ128>>>(th, tl, HID, nullptr, nullptr, 0,
        nullptr, nullptr, 0, HID, W1bh, W1bl, b1b, nullptr, h1h, h1l, N, HH);

    // ---- layer 2 ----
    conv_gather128_bf<<<nwarp_blocks, 256>>>(h1h, rows, deg, ssrc, cbh, cbl, N);
    gemm_mma<128, 0><<<dim3(2, mb), 256, SZ128>>>(cbh, cbl, HH, h1h, h1l, HH,
        xh, xl, D_IN, 304, W2ah, W2al, b2a, nullptr, th, tl, N, HID);
    gemm_mma<128, 0><<<dim3(1, mb), 256, SZ128>>>(th, tl, HID, nullptr, nullptr, 0,
        nullptr, nullptr, 0, HID, W2bh, W2bl, b2b, nullptr, h2h, h2l, N, HH);

    // ---- layer 3 ----
    conv_gather128_bf<<<nwarp_blocks, 256>>>(h2h, rows, deg, ssrc, cbh, cbl, N);
    gemm_mma<128, 0><<<dim3(2, mb), 256, SZ128>>>(cbh, cbl, HH, h2h, h2l, HH,
        xh, xl, D_IN, 304, W3ah, W3al, b3a, nullptr, th, tl, N, HID);
    gemm_mma<64, 2><<<dim3(1, mb), 256, SZ64>>>(th, tl, HID, nullptr, nullptr, 0,
        nullptr, nullptr, 0, HID, W3bh, W3bl, b3b, out, nullptr, nullptr, N, NOUT);
}